// round 3
// baseline (speedup 1.0000x reference)
#include <cuda_runtime.h>
#include <cuda_bf16.h>
#include <math.h>

#define BB 64
#define FF 256
#define TT 1024
#define HH 1024
#define OO 512
#define NB 128   // persistent CTAs for the recurrence (<= 148 SMs -> all resident)

// Scratch (allocation-free rule: __device__ globals)
__device__ float g_Z[(size_t)TT * BB * HH];   // 256MB: Z = x@Wx + b, later overwritten with states, layout [t][b][h]
__device__ float g_ST[2][HH * BB];            // transposed state ping-pong, layout [h][b]
__device__ unsigned g_cnt;
__device__ unsigned g_gen;

// ---------------------------------------------------------------- helpers
__device__ __forceinline__ float2 ffma2(float2 a, float2 b, float2 c) {
    unsigned long long ua = *reinterpret_cast<unsigned long long*>(&a);
    unsigned long long ub = *reinterpret_cast<unsigned long long*>(&b);
    unsigned long long uc = *reinterpret_cast<unsigned long long*>(&c);
    unsigned long long ud;
    asm("fma.rn.f32x2 %0, %1, %2, %3;" : "=l"(ud) : "l"(ua), "l"(ub), "l"(uc));
    return *reinterpret_cast<float2*>(&ud);
}
__device__ __forceinline__ float2 dup2(float s) { return make_float2(s, s); }

__device__ __forceinline__ void grid_barrier() {
    __syncthreads();
    if (threadIdx.x == 0) {
        volatile unsigned* vg = &g_gen;
        unsigned gen = *vg;
        __threadfence();
        if (atomicAdd(&g_cnt, 1u) == NB - 1u) {
            g_cnt = 0u;            // everyone has incremented already; reset before release
            __threadfence();
            *vg = gen + 1u;        // release
        } else {
            while (*vg == gen) { __nanosleep(128); }
        }
        __threadfence();
    }
    __syncthreads();
}

// ---------------------------------------------------------------- Kernel A: Z[t][b][h] = b[h] + sum_f x[b][f][t] * Wx[f][h]
// grid (T/128, H/128, B), 256 threads, 128x128 tile, K-chunks of 32, 8x8 per thread (f32x2 packed)
__global__ void __launch_bounds__(256) zmat_kernel(const float* __restrict__ x,
                                                   const float* __restrict__ Wx,
                                                   const float* __restrict__ bias) {
    __shared__ float xs[32 * 128];   // [f][t]
    __shared__ float ws[32 * 128];   // [f][h]
    int t0 = blockIdx.x * 128;
    int h0 = blockIdx.y * 128;
    int b  = blockIdx.z;
    int tid = threadIdx.x;
    int tt = tid >> 4;    // 0..15 row group (t)
    int th = tid & 15;    // 0..15 col group (h)

    float2 acc[8][4];
    #pragma unroll
    for (int i = 0; i < 8; i++)
        #pragma unroll
        for (int j = 0; j < 4; j++) acc[i][j] = make_float2(0.f, 0.f);

    const float* xb = x + (size_t)b * FF * TT;
    for (int f0 = 0; f0 < FF; f0 += 32) {
        #pragma unroll
        for (int i = tid; i < 4096; i += 256) {
            int f = i >> 7, u = i & 127;
            xs[i] = xb[(f0 + f) * TT + t0 + u];          // coalesced along t
            ws[i] = Wx[(f0 + f) * HH + h0 + u];          // coalesced along h
        }
        __syncthreads();
        #pragma unroll
        for (int k = 0; k < 32; k++) {
            float4 a0 = *reinterpret_cast<const float4*>(xs + k * 128 + tt * 8);
            float4 a1 = *reinterpret_cast<const float4*>(xs + k * 128 + tt * 8 + 4);
            float4 w0 = *reinterpret_cast<const float4*>(ws + k * 128 + th * 8);
            float4 w1 = *reinterpret_cast<const float4*>(ws + k * 128 + th * 8 + 4);
            float2 wp[4] = { make_float2(w0.x, w0.y), make_float2(w0.z, w0.w),
                             make_float2(w1.x, w1.y), make_float2(w1.z, w1.w) };
            float av[8] = { a0.x, a0.y, a0.z, a0.w, a1.x, a1.y, a1.z, a1.w };
            #pragma unroll
            for (int i = 0; i < 8; i++) {
                float2 ad = dup2(av[i]);
                #pragma unroll
                for (int j = 0; j < 4; j++) acc[i][j] = ffma2(ad, wp[j], acc[i][j]);
            }
        }
        __syncthreads();
    }
    float4 bv0 = *reinterpret_cast<const float4*>(bias + h0 + th * 8);
    float4 bv1 = *reinterpret_cast<const float4*>(bias + h0 + th * 8 + 4);
    #pragma unroll
    for (int i = 0; i < 8; i++) {
        int t = t0 + tt * 8 + i;
        float* zp = g_Z + (size_t)t * (BB * HH) + b * HH + h0 + th * 8;
        float4 o0 = make_float4(acc[i][0].x + bv0.x, acc[i][0].y + bv0.y,
                                acc[i][1].x + bv0.z, acc[i][1].y + bv0.w);
        float4 o1 = make_float4(acc[i][2].x + bv1.x, acc[i][2].y + bv1.y,
                                acc[i][3].x + bv1.z, acc[i][3].y + bv1.w);
        *reinterpret_cast<float4*>(zp)     = o0;
        *reinterpret_cast<float4*>(zp + 4) = o1;
    }
}

// ---------------------------------------------------------------- Kernel B: persistent recurrence
// grid = 128 CTAs: (r in {0,1}: 32 batch rows) x (c in 0..63: 16 H cols). Wh col-tile lives in SMEM
// for all 1024 steps. State double-buffered in transposed [h][b] layout for LDG.128 inner-loop reads.
// 8 warps K-split (128 k each), per-thread 4x4 register tile, f32x2 FMAs, SMEM cross-warp reduce.
__global__ void __launch_bounds__(256, 1) rnn_rec_kernel(const float* __restrict__ Wh) {
    extern __shared__ float smem[];
    float* wh_s  = smem;            // [k][16] : 16384 floats (64KB), step-invariant
    float* red_s = smem + 16384;    // [8 warps][512 outputs] : 16KB
    int tid  = threadIdx.x;
    int wid  = tid >> 5, lane = tid & 31;
    int c = blockIdx.x & 63;        // column tile (16 cols)
    int r = blockIdx.x >> 6;        // row half (32 rows)

    for (int i = tid; i < 16384; i += 256) {
        int k = i >> 4, n = i & 15;
        wh_s[i] = Wh[k * HH + c * 16 + n];
    }
    __syncthreads();

    int g8 = lane >> 2;             // m-group: rows 4*g8..4*g8+3
    int ng = lane & 3;              // n-group: cols 4*ng..4*ng+3
    int rowoff = r * 32 + g8 * 4;
    int kbeg = wid << 7;            // this warp's K slice start

    int o  = tid * 2;               // epilogue: 2 outputs per thread
    int em = o >> 4, en = o & 15;
    int brow = r * 32 + em, hcol = c * 16 + en;

    for (int t = 0; t < TT; ++t) {
        float2 acc[4][2];
        #pragma unroll
        for (int i = 0; i < 4; i++) { acc[i][0] = make_float2(0.f, 0.f); acc[i][1] = make_float2(0.f, 0.f); }

        if (t > 0) {
            // prev states, transposed [h][b]
            const float4* sp = reinterpret_cast<const float4*>(g_ST[(t + 1) & 1] + kbeg * BB + rowoff);
            const float*  wp = wh_s + kbeg * 16 + ng * 4;
            #pragma unroll 4
            for (int k = 0; k < 128; ++k) {
                float4 s4 = __ldg(sp); sp += BB / 4;                      // S[k][b0..b3], one 128B line per warp
                float4 wq = *reinterpret_cast<const float4*>(wp); wp += 16; // Wh[k][4ng..4ng+3]
                float2 w0 = make_float2(wq.x, wq.y);
                float2 w1 = make_float2(wq.z, wq.w);
                acc[0][0] = ffma2(dup2(s4.x), w0, acc[0][0]);
                acc[0][1] = ffma2(dup2(s4.x), w1, acc[0][1]);
                acc[1][0] = ffma2(dup2(s4.y), w0, acc[1][0]);
                acc[1][1] = ffma2(dup2(s4.y), w1, acc[1][1]);
                acc[2][0] = ffma2(dup2(s4.z), w0, acc[2][0]);
                acc[2][1] = ffma2(dup2(s4.z), w1, acc[2][1]);
                acc[3][0] = ffma2(dup2(s4.w), w0, acc[3][0]);
                acc[3][1] = ffma2(dup2(s4.w), w1, acc[3][1]);
            }
        }
        // cross-warp reduction of K-split partials
        float* rp = red_s + wid * 512 + (g8 * 4) * 16 + ng * 4;
        #pragma unroll
        for (int i = 0; i < 4; i++) {
            *reinterpret_cast<float2*>(rp + i * 16)     = acc[i][0];
            *reinterpret_cast<float2*>(rp + i * 16 + 2) = acc[i][1];
        }
        __syncthreads();
        {
            float2 v = make_float2(0.f, 0.f);
            #pragma unroll
            for (int w = 0; w < 8; w++) {
                float2 p = *reinterpret_cast<const float2*>(red_s + w * 512 + o);
                v.x += p.x; v.y += p.y;
            }
            float* zp = g_Z + (size_t)t * (BB * HH) + brow * HH + hcol;
            float s0 = tanhf(zp[0] + v.x);
            float s1 = tanhf(zp[1] + v.y);
            zp[0] = s0; zp[1] = s1;                    // overwrite Z with state (feeds kernel C)
            float* stp = g_ST[t & 1];                  // transposed copy for next step's fast reads
            stp[hcol * BB + brow]       = s0;
            stp[(hcol + 1) * BB + brow] = s1;
        }
        __threadfence();
        grid_barrier();
    }
}

// ---------------------------------------------------------------- Kernel C: out[b][t][o] = bout[o] + sum_h S[t*64+b][h] * Wout[h][o]
// rows = flat (t*64+b) (matches g_Z layout), grid (65536/128, 512/128), 128x128 tiles, K-chunks 32
__global__ void __launch_bounds__(256) out_kernel(const float* __restrict__ Wout,
                                                  const float* __restrict__ bout,
                                                  float* __restrict__ out) {
    __shared__ float ss[128 * 33];   // [row][k] padded (conflict-free stage + broadcast reads)
    __shared__ float ws[32 * 128];   // [k][o]
    int r0 = blockIdx.x * 128;
    int o0 = blockIdx.y * 128;
    int tid = threadIdx.x;
    int tt = tid >> 4, th = tid & 15;

    float2 acc[8][4];
    #pragma unroll
    for (int i = 0; i < 8; i++)
        #pragma unroll
        for (int j = 0; j < 4; j++) acc[i][j] = make_float2(0.f, 0.f);

    for (int f0 = 0; f0 < HH; f0 += 32) {
        #pragma unroll
        for (int i = tid; i < 4096; i += 256) {
            int ri = i >> 5, k = i & 31;
            ss[ri * 33 + k] = g_Z[(size_t)(r0 + ri) * HH + f0 + k];   // coalesced along h
            int k2 = i >> 7, oo = i & 127;
            ws[i] = Wout[(f0 + k2) * OO + o0 + oo];                   // coalesced along o
        }
        __syncthreads();
        #pragma unroll
        for (int k = 0; k < 32; k++) {
            float av[8];
            #pragma unroll
            for (int i = 0; i < 8; i++) av[i] = ss[(tt * 8 + i) * 33 + k];
            float4 w0 = *reinterpret_cast<const float4*>(ws + k * 128 + th * 8);
            float4 w1 = *reinterpret_cast<const float4*>(ws + k * 128 + th * 8 + 4);
            float2 wp[4] = { make_float2(w0.x, w0.y), make_float2(w0.z, w0.w),
                             make_float2(w1.x, w1.y), make_float2(w1.z, w1.w) };
            #pragma unroll
            for (int i = 0; i < 8; i++) {
                float2 ad = dup2(av[i]);
                #pragma unroll
                for (int j = 0; j < 4; j++) acc[i][j] = ffma2(ad, wp[j], acc[i][j]);
            }
        }
        __syncthreads();
    }
    float4 bv0 = *reinterpret_cast<const float4*>(bout + o0 + th * 8);
    float4 bv1 = *reinterpret_cast<const float4*>(bout + o0 + th * 8 + 4);
    #pragma unroll
    for (int i = 0; i < 8; i++) {
        int row = r0 + tt * 8 + i;
        int t  = row >> 6;
        int bb = row & 63;
        float* op = out + (size_t)bb * (TT * OO) + t * OO + o0 + th * 8;
        float4 q0 = make_float4(acc[i][0].x + bv0.x, acc[i][0].y + bv0.y,
                                acc[i][1].x + bv0.z, acc[i][1].y + bv0.w);
        float4 q1 = make_float4(acc[i][2].x + bv1.x, acc[i][2].y + bv1.y,
                                acc[i][3].x + bv1.z, acc[i][3].y + bv1.w);
        *reinterpret_cast<float4*>(op)     = q0;
        *reinterpret_cast<float4*>(op + 4) = q1;
    }
}

// ---------------------------------------------------------------- launch
extern "C" void kernel_launch(void* const* d_in, const int* in_sizes, int n_in,
                              void* d_out, int out_size) {
    const float* x    = (const float*)d_in[0];   // (B,F,T)
    const float* Wx   = (const float*)d_in[1];   // (F,H)
    const float* Wh   = (const float*)d_in[2];   // (H,H)
    const float* bv   = (const float*)d_in[3];   // (H,)
    const float* Wout = (const float*)d_in[4];   // (H,O)
    const float* bo   = (const float*)d_in[5];   // (O,)
    float* out = (float*)d_out;                  // (B,T,O)

    (void)in_sizes; (void)n_in; (void)out_size;

    // Phase 1: Z = x@Wx + b for all timesteps (parallel GEMM)
    dim3 ga(TT / 128, HH / 128, BB);
    zmat_kernel<<<ga, 256>>>(x, Wx, bv);

    // Phase 2: persistent sequential recurrence (states overwrite g_Z)
    size_t dyn = (16384 + 4096) * sizeof(float);  // 80KB
    cudaFuncSetAttribute(rnn_rec_kernel, cudaFuncAttributeMaxDynamicSharedMemorySize, (int)(96 * 1024));
    rnn_rec_kernel<<<NB, 256, dyn>>>(Wh);

    // Phase 3: output projection (parallel GEMM)
    dim3 gc((TT * BB) / 128, OO / 128);
    out_kernel<<<gc, 256>>>(Wout, bo, out);
}

// round 4
// speedup vs baseline: 1.5577x; 1.5577x over previous
#include <cuda_runtime.h>
#include <cuda_bf16.h>
#include <math.h>

#define BB 64
#define FF 256
#define TT 1024
#define HH 1024
#define OO 512
#define NB 128   // persistent CTAs for the recurrence (<= 148 SMs -> all resident)

// Scratch (allocation-free rule: __device__ globals)
__device__ float g_Z[(size_t)TT * BB * HH];   // 256MB: Z = x@Wx + b, later overwritten with states, layout [t][b][h]
__device__ float g_ST[2][HH * BB];            // transposed state ping-pong, layout [h][b]
__device__ unsigned g_cnt;
__device__ unsigned g_gen;

// ---------------------------------------------------------------- helpers
__device__ __forceinline__ float2 ffma2(float2 a, float2 b, float2 c) {
    unsigned long long ua = *reinterpret_cast<unsigned long long*>(&a);
    unsigned long long ub = *reinterpret_cast<unsigned long long*>(&b);
    unsigned long long uc = *reinterpret_cast<unsigned long long*>(&c);
    unsigned long long ud;
    asm("fma.rn.f32x2 %0, %1, %2, %3;" : "=l"(ud) : "l"(ua), "l"(ub), "l"(uc));
    return *reinterpret_cast<float2*>(&ud);
}
__device__ __forceinline__ float2 dup2(float s) { return make_float2(s, s); }

__device__ __forceinline__ void cp_async16(float* smem_dst, const float* gmem_src) {
    unsigned s = (unsigned)__cvta_generic_to_shared(smem_dst);
    asm volatile("cp.async.cg.shared.global [%0], [%1], 16;\n" :: "r"(s), "l"(gmem_src));
}
__device__ __forceinline__ void cp_commit() { asm volatile("cp.async.commit_group;\n"); }
template <int N> __device__ __forceinline__ void cp_wait() {
    asm volatile("cp.async.wait_group %0;\n" :: "n"(N));
}

__device__ __forceinline__ void grid_barrier() {
    __syncthreads();
    if (threadIdx.x == 0) {
        volatile unsigned* vg = &g_gen;
        unsigned gen = *vg;
        __threadfence();
        if (atomicAdd(&g_cnt, 1u) == NB - 1u) {
            g_cnt = 0u;
            __threadfence();
            *vg = gen + 1u;        // release
        } else {
            while (*vg == gen) { __nanosleep(64); }
        }
        __threadfence();
    }
    __syncthreads();
}

// ---------------------------------------------------------------- Kernel A: Z[t][b][h] = b[h] + sum_f x[b][f][t] * Wx[f][h]
__global__ void __launch_bounds__(256) zmat_kernel(const float* __restrict__ x,
                                                   const float* __restrict__ Wx,
                                                   const float* __restrict__ bias) {
    __shared__ float xs[32 * 128];   // [f][t]
    __shared__ float ws[32 * 128];   // [f][h]
    int t0 = blockIdx.x * 128;
    int h0 = blockIdx.y * 128;
    int b  = blockIdx.z;
    int tid = threadIdx.x;
    int tt = tid >> 4;
    int th = tid & 15;

    float2 acc[8][4];
    #pragma unroll
    for (int i = 0; i < 8; i++)
        #pragma unroll
        for (int j = 0; j < 4; j++) acc[i][j] = make_float2(0.f, 0.f);

    const float* xb = x + (size_t)b * FF * TT;
    for (int f0 = 0; f0 < FF; f0 += 32) {
        #pragma unroll
        for (int i = tid; i < 4096; i += 256) {
            int f = i >> 7, u = i & 127;
            xs[i] = xb[(f0 + f) * TT + t0 + u];
            ws[i] = Wx[(f0 + f) * HH + h0 + u];
        }
        __syncthreads();
        #pragma unroll
        for (int k = 0; k < 32; k++) {
            float4 a0 = *reinterpret_cast<const float4*>(xs + k * 128 + tt * 8);
            float4 a1 = *reinterpret_cast<const float4*>(xs + k * 128 + tt * 8 + 4);
            float4 w0 = *reinterpret_cast<const float4*>(ws + k * 128 + th * 8);
            float4 w1 = *reinterpret_cast<const float4*>(ws + k * 128 + th * 8 + 4);
            float2 wp[4] = { make_float2(w0.x, w0.y), make_float2(w0.z, w0.w),
                             make_float2(w1.x, w1.y), make_float2(w1.z, w1.w) };
            float av[8] = { a0.x, a0.y, a0.z, a0.w, a1.x, a1.y, a1.z, a1.w };
            #pragma unroll
            for (int i = 0; i < 8; i++) {
                float2 ad = dup2(av[i]);
                #pragma unroll
                for (int j = 0; j < 4; j++) acc[i][j] = ffma2(ad, wp[j], acc[i][j]);
            }
        }
        __syncthreads();
    }
    float4 bv0 = *reinterpret_cast<const float4*>(bias + h0 + th * 8);
    float4 bv1 = *reinterpret_cast<const float4*>(bias + h0 + th * 8 + 4);
    #pragma unroll
    for (int i = 0; i < 8; i++) {
        int t = t0 + tt * 8 + i;
        float* zp = g_Z + (size_t)t * (BB * HH) + b * HH + h0 + th * 8;
        float4 o0 = make_float4(acc[i][0].x + bv0.x, acc[i][0].y + bv0.y,
                                acc[i][1].x + bv0.z, acc[i][1].y + bv0.w);
        float4 o1 = make_float4(acc[i][2].x + bv1.x, acc[i][2].y + bv1.y,
                                acc[i][3].x + bv1.z, acc[i][3].y + bv1.w);
        *reinterpret_cast<float4*>(zp)     = o0;
        *reinterpret_cast<float4*>(zp + 4) = o1;
    }
}

// ---------------------------------------------------------------- Kernel B: persistent recurrence (SMEM-staged state)
// 128 CTAs: (r in {0,1}: 32 batch rows) x (c in 0..63: 16 H cols).
// Per step: cp.async-stage prev state slice [1024 k][32 b] (128KB) in 4 chunked groups,
// compute chunk-wise out of SMEM (LDS+FFMA2 only), cross-warp reduce, coalesced epilogue.
// SMEM: Wh tile 64KB (step-invariant) + state 128KB + reduce 16KB + fin ~2KB ~= 210KB.
__global__ void __launch_bounds__(256, 1) rnn_rec_kernel(const float* __restrict__ Wh) {
    extern __shared__ float smem[];
    float* wh_s  = smem;                    // [k][16]   16384 floats
    float* st_s  = smem + 16384;            // [k][32]   32768 floats
    float* red_s = smem + 16384 + 32768;    // [8][512]   4096 floats
    float* fin   = red_s + 4096;            // [32][17]    544 floats
    int tid  = threadIdx.x;
    int wid  = tid >> 5, lane = tid & 31;
    int c = blockIdx.x & 63;                // column tile (16 cols)
    int r = blockIdx.x >> 6;                // row half (32 rows)
    int r32 = r * 32;

    for (int i = tid; i < 16384; i += 256) {
        int k = i >> 4, n = i & 15;
        wh_s[i] = Wh[k * HH + c * 16 + n];
    }
    __syncthreads();

    int g8 = lane >> 2;                     // m-group: rows 4*g8..4*g8+3
    int ng = lane & 3;                      // n-group: cols 4*ng..4*ng+3

    // epilogue mapping (row-major): o = tid*2 -> (em, en)
    int o  = tid * 2;
    int em = o >> 4, en = o & 15;
    int brow = r32 + em, hcol = c * 16 + en;
    // transposed-store mapping (col-major): j = tid*2 -> (hl, em2)
    int j   = tid * 2;
    int hl  = j >> 5, em2 = j & 31;

    for (int t = 0; t < TT; ++t) {
        float2 acc[4][2];
        #pragma unroll
        for (int i = 0; i < 4; i++) { acc[i][0] = make_float2(0.f, 0.f); acc[i][1] = make_float2(0.f, 0.f); }

        if (t > 0) {
            const float* prev = g_ST[(t + 1) & 1];
            // issue 4 chunked staging groups (each: 256 k-rows x 32 b = 32KB)
            #pragma unroll
            for (int ch = 0; ch < 4; ch++) {
                #pragma unroll
                for (int it = 0; it < 8; it++) {
                    int i = ch * 2048 + it * 256 + tid;       // float4 index
                    int row = i >> 3, q = (i & 7) * 4;
                    cp_async16(st_s + row * 32 + q, prev + row * BB + r32 + q);
                }
                cp_commit();
            }
            // compute chunk-wise; warp w handles k in [ch*256 + w*32, +32)
            #pragma unroll
            for (int ch = 0; ch < 4; ch++) {
                if (ch == 0) cp_wait<3>();
                else if (ch == 1) cp_wait<2>();
                else if (ch == 2) cp_wait<1>();
                else cp_wait<0>();
                __syncthreads();
                int kb = ch * 256 + wid * 32;
                const float* sp = st_s + kb * 32 + g8 * 4;
                const float* wp = wh_s + kb * 16 + ng * 4;
                #pragma unroll
                for (int k = 0; k < 32; ++k) {
                    float4 s4 = *reinterpret_cast<const float4*>(sp); sp += 32;
                    float4 wq = *reinterpret_cast<const float4*>(wp); wp += 16;
                    float2 w0 = make_float2(wq.x, wq.y);
                    float2 w1 = make_float2(wq.z, wq.w);
                    acc[0][0] = ffma2(dup2(s4.x), w0, acc[0][0]);
                    acc[0][1] = ffma2(dup2(s4.x), w1, acc[0][1]);
                    acc[1][0] = ffma2(dup2(s4.y), w0, acc[1][0]);
                    acc[1][1] = ffma2(dup2(s4.y), w1, acc[1][1]);
                    acc[2][0] = ffma2(dup2(s4.z), w0, acc[2][0]);
                    acc[2][1] = ffma2(dup2(s4.z), w1, acc[2][1]);
                    acc[3][0] = ffma2(dup2(s4.w), w0, acc[3][0]);
                    acc[3][1] = ffma2(dup2(s4.w), w1, acc[3][1]);
                }
            }
        }

        // cross-warp reduction of K-split partials
        float* rp = red_s + wid * 512 + (g8 * 4) * 16 + ng * 4;
        #pragma unroll
        for (int i = 0; i < 4; i++) {
            *reinterpret_cast<float2*>(rp + i * 16)     = acc[i][0];
            *reinterpret_cast<float2*>(rp + i * 16 + 2) = acc[i][1];
        }
        __syncthreads();
        {
            float2 v = make_float2(0.f, 0.f);
            #pragma unroll
            for (int w = 0; w < 8; w++) {
                float2 p = *reinterpret_cast<const float2*>(red_s + w * 512 + o);
                v.x += p.x; v.y += p.y;
            }
            float* zp = g_Z + (size_t)t * (BB * HH) + (size_t)brow * HH + hcol;
            float s0 = tanhf(zp[0] + v.x);
            float s1 = tanhf(zp[1] + v.y);
            *reinterpret_cast<float2*>(zp) = make_float2(s0, s1);   // coalesced (feeds kernel C)
            fin[em * 17 + en]     = s0;
            fin[em * 17 + en + 1] = s1;
        }
        __syncthreads();
        {
            // coalesced transposed store: thread -> (col hl, rows em2, em2+1)
            float a  = fin[em2 * 17 + hl];
            float b2 = fin[(em2 + 1) * 17 + hl];
            float* stp = g_ST[t & 1] + (size_t)(c * 16 + hl) * BB + r32 + em2;
            *reinterpret_cast<float2*>(stp) = make_float2(a, b2);
        }
        __threadfence();
        grid_barrier();
    }
}

// ---------------------------------------------------------------- Kernel C: out[b][t][o] = bout[o] + sum_h S[row][h] * Wout[h][o]
__global__ void __launch_bounds__(256) out_kernel(const float* __restrict__ Wout,
                                                  const float* __restrict__ bout,
                                                  float* __restrict__ out) {
    __shared__ float ss[128 * 33];   // [row][k] padded
    __shared__ float ws[32 * 128];   // [k][o]
    int r0 = blockIdx.x * 128;
    int o0 = blockIdx.y * 128;
    int tid = threadIdx.x;
    int tt = tid >> 4, th = tid & 15;

    float2 acc[8][4];
    #pragma unroll
    for (int i = 0; i < 8; i++)
        #pragma unroll
        for (int j = 0; j < 4; j++) acc[i][j] = make_float2(0.f, 0.f);

    for (int f0 = 0; f0 < HH; f0 += 32) {
        #pragma unroll
        for (int i = tid; i < 4096; i += 256) {
            int ri = i >> 5, k = i & 31;
            ss[ri * 33 + k] = g_Z[(size_t)(r0 + ri) * HH + f0 + k];
            int k2 = i >> 7, oo = i & 127;
            ws[i] = Wout[(f0 + k2) * OO + o0 + oo];
        }
        __syncthreads();
        #pragma unroll
        for (int k = 0; k < 32; k++) {
            float av[8];
            #pragma unroll
            for (int i = 0; i < 8; i++) av[i] = ss[(tt * 8 + i) * 33 + k];
            float4 w0 = *reinterpret_cast<const float4*>(ws + k * 128 + th * 8);
            float4 w1 = *reinterpret_cast<const float4*>(ws + k * 128 + th * 8 + 4);
            float2 wp[4] = { make_float2(w0.x, w0.y), make_float2(w0.z, w0.w),
                             make_float2(w1.x, w1.y), make_float2(w1.z, w1.w) };
            #pragma unroll
            for (int i = 0; i < 8; i++) {
                float2 ad = dup2(av[i]);
                #pragma unroll
                for (int j = 0; j < 4; j++) acc[i][j] = ffma2(ad, wp[j], acc[i][j]);
            }
        }
        __syncthreads();
    }
    float4 bv0 = *reinterpret_cast<const float4*>(bout + o0 + th * 8);
    float4 bv1 = *reinterpret_cast<const float4*>(bout + o0 + th * 8 + 4);
    #pragma unroll
    for (int i = 0; i < 8; i++) {
        int row = r0 + tt * 8 + i;
        int t  = row >> 6;
        int bb = row & 63;
        float* op = out + (size_t)bb * (TT * OO) + t * OO + o0 + th * 8;
        float4 q0 = make_float4(acc[i][0].x + bv0.x, acc[i][0].y + bv0.y,
                                acc[i][1].x + bv0.z, acc[i][1].y + bv0.w);
        float4 q1 = make_float4(acc[i][2].x + bv1.x, acc[i][2].y + bv1.y,
                                acc[i][3].x + bv1.z, acc[i][3].y + bv1.w);
        *reinterpret_cast<float4*>(op)     = q0;
        *reinterpret_cast<float4*>(op + 4) = q1;
    }
}

// ---------------------------------------------------------------- launch
extern "C" void kernel_launch(void* const* d_in, const int* in_sizes, int n_in,
                              void* d_out, int out_size) {
    const float* x    = (const float*)d_in[0];   // (B,F,T)
    const float* Wx   = (const float*)d_in[1];   // (F,H)
    const float* Wh   = (const float*)d_in[2];   // (H,H)
    const float* bv   = (const float*)d_in[3];   // (H,)
    const float* Wout = (const float*)d_in[4];   // (H,O)
    const float* bo   = (const float*)d_in[5];   // (O,)
    float* out = (float*)d_out;                  // (B,T,O)

    (void)in_sizes; (void)n_in; (void)out_size;

    // Phase 1: Z = x@Wx + b for all timesteps (parallel GEMM)
    dim3 ga(TT / 128, HH / 128, BB);
    zmat_kernel<<<ga, 256>>>(x, Wx, bv);

    // Phase 2: persistent sequential recurrence (states overwrite g_Z)
    size_t dyn = (size_t)(16384 + 32768 + 4096 + 544) * sizeof(float);  // ~210KB
    cudaFuncSetAttribute(rnn_rec_kernel, cudaFuncAttributeMaxDynamicSharedMemorySize, 232448);
    rnn_rec_kernel<<<NB, 256, dyn>>>(Wh);

    // Phase 3: output projection (parallel GEMM)
    dim3 gc((TT * BB) / 128, OO / 128);
    out_kernel<<<gc, 256>>>(Wout, bo, out);
}

// round 5
// speedup vs baseline: 1.7583x; 1.1288x over previous
#include <cuda_runtime.h>
#include <cuda_bf16.h>
#include <math.h>
#include <stdint.h>

#define BB 64
#define FF 256
#define TT 1024
#define HH 1024
#define OO 512
#define NB 128   // persistent CTAs: 4 batch-row groups x 32 H-col tiles (<=148 -> co-resident)

// Scratch (allocation-free rule: __device__ globals)
__device__ float g_Z[(size_t)TT * BB * HH];     // Z = x@Wx + b, later overwritten with states, [t][b][h]
__device__ float g_ST2[2][4][HH * 16];          // transposed state ping-pong, [buf][r-group][h][16 b] (contiguous per-CTA slice)
__device__ unsigned g_cnt;
__device__ unsigned g_gen;

// ---------------------------------------------------------------- helpers
__device__ __forceinline__ float2 ffma2(float2 a, float2 b, float2 c) {
    unsigned long long ua = *reinterpret_cast<unsigned long long*>(&a);
    unsigned long long ub = *reinterpret_cast<unsigned long long*>(&b);
    unsigned long long uc = *reinterpret_cast<unsigned long long*>(&c);
    unsigned long long ud;
    asm("fma.rn.f32x2 %0, %1, %2, %3;" : "=l"(ud) : "l"(ua), "l"(ub), "l"(uc));
    return *reinterpret_cast<float2*>(&ud);
}
__device__ __forceinline__ float2 dup2(float s) { return make_float2(s, s); }

__device__ __forceinline__ void cp_async16(float* smem_dst, const float* gmem_src) {
    unsigned s = (unsigned)__cvta_generic_to_shared(smem_dst);
    asm volatile("cp.async.cg.shared.global [%0], [%1], 16;\n" :: "r"(s), "l"(gmem_src));
}
__device__ __forceinline__ void cp_commit() { asm volatile("cp.async.commit_group;\n"); }
template <int N> __device__ __forceinline__ void cp_wait() {
    asm volatile("cp.async.wait_group %0;\n" :: "n"(N));
}

__device__ __forceinline__ void mbar_init(uint32_t mb, uint32_t count) {
    asm volatile("mbarrier.init.shared.b64 [%0], %1;" :: "r"(mb), "r"(count) : "memory");
}
__device__ __forceinline__ void mbar_expect_tx(uint32_t mb, uint32_t bytes) {
    asm volatile("mbarrier.arrive.expect_tx.shared.b64 _, [%0], %1;" :: "r"(mb), "r"(bytes) : "memory");
}
__device__ __forceinline__ void bulk_g2s(uint32_t dst_smem, const float* src, uint32_t bytes, uint32_t mb) {
    asm volatile("cp.async.bulk.shared::cluster.global.mbarrier::complete_tx::bytes [%0], [%1], %2, [%3];"
                 :: "r"(dst_smem), "l"(src), "r"(bytes), "r"(mb) : "memory");
}
__device__ __forceinline__ void mbar_wait(uint32_t mb, int ph) {
    asm volatile(
        "{\n\t"
        ".reg .pred P;\n\t"
        "W%=:\n\t"
        "mbarrier.try_wait.parity.acquire.cta.shared::cta.b64 P, [%0], %1, 0x989680;\n\t"
        "@P bra D%=;\n\t"
        "bra W%=;\n\t"
        "D%=:\n\t"
        "}" :: "r"(mb), "r"(ph) : "memory");
}

__device__ __forceinline__ void grid_barrier() {
    __syncthreads();
    if (threadIdx.x == 0) {
        unsigned gen;
        asm volatile("ld.acquire.gpu.global.u32 %0, [%1];" : "=r"(gen) : "l"(&g_gen) : "memory");
        asm volatile("fence.acq_rel.gpu;" ::: "memory");
        unsigned prev = atomicAdd(&g_cnt, 1u);
        if (prev == NB - 1u) {
            g_cnt = 0u;
            unsigned ng = gen + 1u;
            asm volatile("st.release.gpu.global.u32 [%0], %1;" :: "l"(&g_gen), "r"(ng) : "memory");
        } else {
            unsigned cur;
            do {
                __nanosleep(32);
                asm volatile("ld.acquire.gpu.global.u32 %0, [%1];" : "=r"(cur) : "l"(&g_gen) : "memory");
            } while (cur == gen);
        }
    }
    __syncthreads();
}

// ---------------------------------------------------------------- Kernel A: Z[t][b][h] = b[h] + sum_f x[b][f][t] * Wx[f][h]
// Double-buffered cp.async staging, 128x128 tile, 8 K-chunks of 32.
__global__ void __launch_bounds__(256) zmat_kernel(const float* __restrict__ x,
                                                   const float* __restrict__ Wx,
                                                   const float* __restrict__ bias) {
    extern __shared__ float dsm[];
    float* xs = dsm;           // [2][32][128]
    float* ws = dsm + 8192;    // [2][32][128]
    int t0 = blockIdx.x * 128;
    int h0 = blockIdx.y * 128;
    int b  = blockIdx.z;
    int tid = threadIdx.x;
    int tt = tid >> 4;
    int th = tid & 15;
    const float* xb = x + (size_t)b * FF * TT;

    float2 acc[8][4];
    #pragma unroll
    for (int i = 0; i < 8; i++)
        #pragma unroll
        for (int j = 0; j < 4; j++) acc[i][j] = make_float2(0.f, 0.f);

    // stage chunk ci into buffer buf
    auto issue = [&](int ci, int buf) {
        int f0 = ci * 32;
        float* xd = xs + buf * 4096;
        float* wd = ws + buf * 4096;
        #pragma unroll
        for (int it = 0; it < 4; it++) {
            int idx = it * 256 + tid;          // float4 index, 1024 total
            int f = idx >> 5, u = (idx & 31) * 4;
            cp_async16(xd + f * 128 + u, xb + (f0 + f) * TT + t0 + u);
            cp_async16(wd + f * 128 + u, Wx + (f0 + f) * HH + h0 + u);
        }
        cp_commit();
    };

    issue(0, 0);
    for (int ci = 0; ci < 8; ci++) {
        if (ci < 7) { issue(ci + 1, (ci + 1) & 1); cp_wait<1>(); }
        else cp_wait<0>();
        __syncthreads();
        const float* xc = xs + (ci & 1) * 4096;
        const float* wc = ws + (ci & 1) * 4096;
        #pragma unroll
        for (int k = 0; k < 32; k++) {
            float4 a0 = *reinterpret_cast<const float4*>(xc + k * 128 + tt * 8);
            float4 a1 = *reinterpret_cast<const float4*>(xc + k * 128 + tt * 8 + 4);
            float4 w0 = *reinterpret_cast<const float4*>(wc + k * 128 + th * 8);
            float4 w1 = *reinterpret_cast<const float4*>(wc + k * 128 + th * 8 + 4);
            float2 wp[4] = { make_float2(w0.x, w0.y), make_float2(w0.z, w0.w),
                             make_float2(w1.x, w1.y), make_float2(w1.z, w1.w) };
            float av[8] = { a0.x, a0.y, a0.z, a0.w, a1.x, a1.y, a1.z, a1.w };
            #pragma unroll
            for (int i = 0; i < 8; i++) {
                float2 ad = dup2(av[i]);
                #pragma unroll
                for (int j = 0; j < 4; j++) acc[i][j] = ffma2(ad, wp[j], acc[i][j]);
            }
        }
        __syncthreads();
    }
    float4 bv0 = *reinterpret_cast<const float4*>(bias + h0 + th * 8);
    float4 bv1 = *reinterpret_cast<const float4*>(bias + h0 + th * 8 + 4);
    #pragma unroll
    for (int i = 0; i < 8; i++) {
        int t = t0 + tt * 8 + i;
        float* zp = g_Z + (size_t)t * (BB * HH) + b * HH + h0 + th * 8;
        float4 o0 = make_float4(acc[i][0].x + bv0.x, acc[i][0].y + bv0.y,
                                acc[i][1].x + bv0.z, acc[i][1].y + bv0.w);
        float4 o1 = make_float4(acc[i][2].x + bv1.x, acc[i][2].y + bv1.y,
                                acc[i][3].x + bv1.z, acc[i][3].y + bv1.w);
        *reinterpret_cast<float4*>(zp)     = o0;
        *reinterpret_cast<float4*>(zp + 4) = o1;
    }
}

// ---------------------------------------------------------------- Kernel B: persistent recurrence (TMA-staged state)
// 128 CTAs: (r in 0..3: 16 batch rows) x (c in 0..31: 32 H cols).
// Wh tile [1024][32] (128KB) in SMEM for all steps. Per step: 4 x 16KB cp.async.bulk
// stage the contiguous prev-state slice [1024][16] (64KB); compute chunk-wise out of SMEM.
__global__ void __launch_bounds__(256, 1) rnn_rec_kernel(const float* __restrict__ Wh) {
    extern __shared__ float smem[];
    // [0..16): 4 mbarriers (8B each, 16B-aligned base)
    float* wh_s  = smem + 16;               // [k][32]  32768 floats (128KB)
    float* st_s  = wh_s + 32768;            // [k][16]  16384 floats (64KB)
    float* red_s = st_s + 16384;            // [8][512]  4096 floats (16KB)
    float* fin   = red_s + 4096;            // [16][33]   528 floats
    uint32_t mbar0 = (uint32_t)__cvta_generic_to_shared(smem);

    int tid  = threadIdx.x;
    int wid  = tid >> 5, lane = tid & 31;
    int c = blockIdx.x & 31;                // column tile (32 cols)
    int r = blockIdx.x >> 5;                // batch row group (16 rows)
    int r16 = r * 16;

    if (tid == 0) {
        #pragma unroll
        for (int ch = 0; ch < 4; ch++) mbar_init(mbar0 + ch * 8, 1);
    }
    for (int i = tid; i < 32768; i += 256) {
        int k = i >> 5, n = i & 31;
        wh_s[i] = Wh[k * HH + c * 32 + n];
    }
    __syncthreads();

    int rg = lane >> 3;                     // b-group: rows 4*rg..4*rg+3
    int cg = lane & 7;                      // h-group: cols 4*cg..4*cg+3

    // epilogue mapping (row-major over 16x32 tile)
    int o  = tid * 2;
    int em = o >> 5, en = o & 31;
    int brow = r16 + em, hcol = c * 32 + en;
    // transposed-store mapping (col-major)
    int j2 = tid * 2;
    int hl = j2 >> 4, em2 = j2 & 15;

    for (int t = 0; t < TT; ++t) {
        float2 acc[4][2];
        #pragma unroll
        for (int i = 0; i < 4; i++) { acc[i][0] = make_float2(0.f, 0.f); acc[i][1] = make_float2(0.f, 0.f); }

        if (t > 0) {
            int ph = (t - 1) & 1;
            if (tid == 0) {
                asm volatile("fence.proxy.async;" ::: "memory");
                const float* src = g_ST2[(t + 1) & 1][r];
                #pragma unroll
                for (int ch = 0; ch < 4; ch++) {
                    uint32_t mb = mbar0 + ch * 8;
                    mbar_expect_tx(mb, 16384u);
                    uint32_t dst = (uint32_t)__cvta_generic_to_shared(st_s + ch * 4096);
                    bulk_g2s(dst, src + ch * 4096, 16384u, mb);
                }
            }
            #pragma unroll
            for (int ch = 0; ch < 4; ch++) {
                mbar_wait(mbar0 + ch * 8, ph);
                int kb = ch * 256 + wid * 32;
                const float* sp = st_s + kb * 16 + rg * 4;
                const float* wp = wh_s + kb * 32 + cg * 4;
                #pragma unroll
                for (int k = 0; k < 32; ++k) {
                    float4 s4 = *reinterpret_cast<const float4*>(sp); sp += 16;
                    float4 wq = *reinterpret_cast<const float4*>(wp); wp += 32;
                    float2 w0 = make_float2(wq.x, wq.y);
                    float2 w1 = make_float2(wq.z, wq.w);
                    acc[0][0] = ffma2(dup2(s4.x), w0, acc[0][0]);
                    acc[0][1] = ffma2(dup2(s4.x), w1, acc[0][1]);
                    acc[1][0] = ffma2(dup2(s4.y), w0, acc[1][0]);
                    acc[1][1] = ffma2(dup2(s4.y), w1, acc[1][1]);
                    acc[2][0] = ffma2(dup2(s4.z), w0, acc[2][0]);
                    acc[2][1] = ffma2(dup2(s4.z), w1, acc[2][1]);
                    acc[3][0] = ffma2(dup2(s4.w), w0, acc[3][0]);
                    acc[3][1] = ffma2(dup2(s4.w), w1, acc[3][1]);
                }
            }
        }

        // cross-warp reduction of K-split partials
        float* rp = red_s + wid * 512 + (rg * 4) * 32 + cg * 4;
        #pragma unroll
        for (int i = 0; i < 4; i++) {
            *reinterpret_cast<float2*>(rp + i * 32)     = acc[i][0];
            *reinterpret_cast<float2*>(rp + i * 32 + 2) = acc[i][1];
        }
        __syncthreads();
        {
            float2 v = make_float2(0.f, 0.f);
            #pragma unroll
            for (int w = 0; w < 8; w++) {
                float2 p = *reinterpret_cast<const float2*>(red_s + w * 512 + o);
                v.x += p.x; v.y += p.y;
            }
            float* zp = g_Z + (size_t)t * (BB * HH) + (size_t)brow * HH + hcol;
            float s0 = tanhf(zp[0] + v.x);
            float s1 = tanhf(zp[1] + v.y);
            *reinterpret_cast<float2*>(zp) = make_float2(s0, s1);   // coalesced (feeds kernel C)
            fin[em * 33 + en]     = s0;
            fin[em * 33 + en + 1] = s1;
        }
        __syncthreads();
        {
            float a  = fin[em2 * 33 + hl];
            float b2 = fin[(em2 + 1) * 33 + hl];
            float* stp = g_ST2[t & 1][r] + (size_t)(c * 32 + hl) * 16 + em2;
            *reinterpret_cast<float2*>(stp) = make_float2(a, b2);
        }
        grid_barrier();
    }
}

// ---------------------------------------------------------------- Kernel C: out[b][t][o] = bout[o] + sum_h S[row][h] * Wout[h][o]
// Double-buffered cp.async staging, 32 K-chunks of 32.
__global__ void __launch_bounds__(256) out_kernel(const float* __restrict__ Wout,
                                                  const float* __restrict__ bout,
                                                  float* __restrict__ out) {
    extern __shared__ float dsm[];
    float* ss = dsm;           // [2][128][32]
    float* ws = dsm + 8192;    // [2][32][128]
    int r0 = blockIdx.x * 128;
    int o0 = blockIdx.y * 128;
    int tid = threadIdx.x;
    int tt = tid >> 4, th = tid & 15;

    float2 acc[8][4];
    #pragma unroll
    for (int i = 0; i < 8; i++)
        #pragma unroll
        for (int j = 0; j < 4; j++) acc[i][j] = make_float2(0.f, 0.f);

    auto issue = [&](int ci, int buf) {
        int f0 = ci * 32;
        float* sd = ss + buf * 4096;
        float* wd = ws + buf * 4096;
        #pragma unroll
        for (int it = 0; it < 4; it++) {
            int idx = it * 256 + tid;              // float4 index
            int ri = idx >> 3, kq = (idx & 7) * 4;
            cp_async16(sd + ri * 32 + kq, g_Z + (size_t)(r0 + ri) * HH + f0 + kq);
            int f = idx >> 5, u = (idx & 31) * 4;
            cp_async16(wd + f * 128 + u, Wout + (f0 + f) * OO + o0 + u);
        }
        cp_commit();
    };

    issue(0, 0);
    for (int ci = 0; ci < 32; ci++) {
        if (ci < 31) { issue(ci + 1, (ci + 1) & 1); cp_wait<1>(); }
        else cp_wait<0>();
        __syncthreads();
        const float* sc = ss + (ci & 1) * 4096;
        const float* wc = ws + (ci & 1) * 4096;
        #pragma unroll
        for (int k = 0; k < 32; k++) {
            float av[8];
            #pragma unroll
            for (int i = 0; i < 8; i++) av[i] = sc[(tt * 8 + i) * 32 + k];
            float4 w0 = *reinterpret_cast<const float4*>(wc + k * 128 + th * 8);
            float4 w1 = *reinterpret_cast<const float4*>(wc + k * 128 + th * 8 + 4);
            float2 wp[4] = { make_float2(w0.x, w0.y), make_float2(w0.z, w0.w),
                             make_float2(w1.x, w1.y), make_float2(w1.z, w1.w) };
            #pragma unroll
            for (int i = 0; i < 8; i++) {
                float2 ad = dup2(av[i]);
                #pragma unroll
                for (int j = 0; j < 4; j++) acc[i][j] = ffma2(ad, wp[j], acc[i][j]);
            }
        }
        __syncthreads();
    }
    float4 bv0 = *reinterpret_cast<const float4*>(bout + o0 + th * 8);
    float4 bv1 = *reinterpret_cast<const float4*>(bout + o0 + th * 8 + 4);
    #pragma unroll
    for (int i = 0; i < 8; i++) {
        int row = r0 + tt * 8 + i;
        int t  = row >> 6;
        int bb = row & 63;
        float* op = out + (size_t)bb * (TT * OO) + t * OO + o0 + th * 8;
        float4 q0 = make_float4(acc[i][0].x + bv0.x, acc[i][0].y + bv0.y,
                                acc[i][1].x + bv0.z, acc[i][1].y + bv0.w);
        float4 q1 = make_float4(acc[i][2].x + bv1.x, acc[i][2].y + bv1.y,
                                acc[i][3].x + bv1.z, acc[i][3].y + bv1.w);
        *reinterpret_cast<float4*>(op)     = q0;
        *reinterpret_cast<float4*>(op + 4) = q1;
    }
}

// ---------------------------------------------------------------- launch
extern "C" void kernel_launch(void* const* d_in, const int* in_sizes, int n_in,
                              void* d_out, int out_size) {
    const float* x    = (const float*)d_in[0];   // (B,F,T)
    const float* Wx   = (const float*)d_in[1];   // (F,H)
    const float* Wh   = (const float*)d_in[2];   // (H,H)
    const float* bv   = (const float*)d_in[3];   // (H,)
    const float* Wout = (const float*)d_in[4];   // (H,O)
    const float* bo   = (const float*)d_in[5];   // (O,)
    float* out = (float*)d_out;                  // (B,T,O)

    (void)in_sizes; (void)n_in; (void)out_size;

    // Phase 1: Z = x@Wx + b (parallel GEMM, double-buffered)
    cudaFuncSetAttribute(zmat_kernel, cudaFuncAttributeMaxDynamicSharedMemorySize, 65536);
    dim3 ga(TT / 128, HH / 128, BB);
    zmat_kernel<<<ga, 256, 65536>>>(x, Wx, bv);

    // Phase 2: persistent sequential recurrence (TMA bulk staging)
    size_t dyn = (size_t)(16 + 32768 + 16384 + 4096 + 528) * sizeof(float);  // ~215KB
    cudaFuncSetAttribute(rnn_rec_kernel, cudaFuncAttributeMaxDynamicSharedMemorySize, 232448);
    rnn_rec_kernel<<<NB, 256, dyn>>>(Wh);

    // Phase 3: output projection (parallel GEMM, double-buffered)
    cudaFuncSetAttribute(out_kernel, cudaFuncAttributeMaxDynamicSharedMemorySize, 65536);
    dim3 gc((TT * BB) / 128, OO / 128);
    out_kernel<<<gc, 256, 65536>>>(Wout, bo, out);
}

// round 6
// speedup vs baseline: 1.7628x; 1.0026x over previous
#include <cuda_runtime.h>
#include <cuda_bf16.h>
#include <math.h>
#include <stdint.h>

#define BB 64
#define FF 256
#define TT 1024
#define HH 1024
#define OO 512
#define NB 128   // persistent CTAs: 4 batch-row groups x 32 H-col tiles (<=148 -> co-resident)

// Scratch (allocation-free rule: __device__ globals)
__device__ float g_Z[(size_t)TT * BB * HH];     // Z = x@Wx + b, later overwritten with states, [t][b][h]
__device__ float g_ST2[2][4][HH * 16];          // transposed state ping-pong, [buf][r-group][h][16 b]
__device__ unsigned g_cnt4[4 * 32];             // per-r-group barrier counters (128B apart)
__device__ unsigned g_gen4[4 * 32];             // per-r-group barrier generations (128B apart)

// ---------------------------------------------------------------- helpers
__device__ __forceinline__ float2 ffma2(float2 a, float2 b, float2 c) {
    unsigned long long ua = *reinterpret_cast<unsigned long long*>(&a);
    unsigned long long ub = *reinterpret_cast<unsigned long long*>(&b);
    unsigned long long uc = *reinterpret_cast<unsigned long long*>(&c);
    unsigned long long ud;
    asm("fma.rn.f32x2 %0, %1, %2, %3;" : "=l"(ud) : "l"(ua), "l"(ub), "l"(uc));
    return *reinterpret_cast<float2*>(&ud);
}
__device__ __forceinline__ float2 dup2(float s) { return make_float2(s, s); }

__device__ __forceinline__ void cp_async16(float* smem_dst, const float* gmem_src) {
    unsigned s = (unsigned)__cvta_generic_to_shared(smem_dst);
    asm volatile("cp.async.cg.shared.global [%0], [%1], 16;\n" :: "r"(s), "l"(gmem_src));
}
__device__ __forceinline__ void cp_commit() { asm volatile("cp.async.commit_group;\n"); }
template <int N> __device__ __forceinline__ void cp_wait() {
    asm volatile("cp.async.wait_group %0;\n" :: "n"(N));
}

__device__ __forceinline__ void mbar_init(uint32_t mb, uint32_t count) {
    asm volatile("mbarrier.init.shared.b64 [%0], %1;" :: "r"(mb), "r"(count) : "memory");
}
__device__ __forceinline__ void mbar_expect_tx(uint32_t mb, uint32_t bytes) {
    asm volatile("mbarrier.arrive.expect_tx.shared.b64 _, [%0], %1;" :: "r"(mb), "r"(bytes) : "memory");
}
__device__ __forceinline__ void bulk_g2s(uint32_t dst_smem, const float* src, uint32_t bytes, uint32_t mb) {
    asm volatile("cp.async.bulk.shared::cluster.global.mbarrier::complete_tx::bytes [%0], [%1], %2, [%3];"
                 :: "r"(dst_smem), "l"(src), "r"(bytes), "r"(mb) : "memory");
}
__device__ __forceinline__ void mbar_wait(uint32_t mb, int ph) {
    asm volatile(
        "{\n\t"
        ".reg .pred P;\n\t"
        "W%=:\n\t"
        "mbarrier.try_wait.parity.acquire.cta.shared::cta.b64 P, [%0], %1, 0x989680;\n\t"
        "@P bra D%=;\n\t"
        "bra W%=;\n\t"
        "D%=:\n\t"
        "}" :: "r"(mb), "r"(ph) : "memory");
}

// barrier among the 32 CTAs of one r-group (independent dependency domains)
__device__ __forceinline__ void group_barrier(int r) {
    __syncthreads();
    if (threadIdx.x == 0) {
        unsigned* cnt = &g_cnt4[r * 32];
        unsigned* gen = &g_gen4[r * 32];
        unsigned g;
        asm volatile("ld.acquire.gpu.global.u32 %0, [%1];" : "=r"(g) : "l"(gen) : "memory");
        asm volatile("fence.acq_rel.gpu;" ::: "memory");
        unsigned prev = atomicAdd(cnt, 1u);
        if (prev == 31u) {
            *cnt = 0u;
            unsigned ng = g + 1u;
            asm volatile("st.release.gpu.global.u32 [%0], %1;" :: "l"(gen), "r"(ng) : "memory");
        } else {
            unsigned cur;
            do {
                __nanosleep(32);
                asm volatile("ld.acquire.gpu.global.u32 %0, [%1];" : "=r"(cur) : "l"(gen) : "memory");
            } while (cur == g);
        }
    }
    __syncthreads();
}

// ---------------------------------------------------------------- Kernel A: Z[t][b][h] = b[h] + sum_f x[b][f][t] * Wx[f][h]
__global__ void __launch_bounds__(256) zmat_kernel(const float* __restrict__ x,
                                                   const float* __restrict__ Wx,
                                                   const float* __restrict__ bias) {
    extern __shared__ float dsm[];
    float* xs = dsm;           // [2][32][128]
    float* ws = dsm + 8192;    // [2][32][128]
    int t0 = blockIdx.x * 128;
    int h0 = blockIdx.y * 128;
    int b  = blockIdx.z;
    int tid = threadIdx.x;
    int tt = tid >> 4;
    int th = tid & 15;
    const float* xb = x + (size_t)b * FF * TT;

    float2 acc[8][4];
    #pragma unroll
    for (int i = 0; i < 8; i++)
        #pragma unroll
        for (int j = 0; j < 4; j++) acc[i][j] = make_float2(0.f, 0.f);

    auto issue = [&](int ci, int buf) {
        int f0 = ci * 32;
        float* xd = xs + buf * 4096;
        float* wd = ws + buf * 4096;
        #pragma unroll
        for (int it = 0; it < 4; it++) {
            int idx = it * 256 + tid;
            int f = idx >> 5, u = (idx & 31) * 4;
            cp_async16(xd + f * 128 + u, xb + (f0 + f) * TT + t0 + u);
            cp_async16(wd + f * 128 + u, Wx + (f0 + f) * HH + h0 + u);
        }
        cp_commit();
    };

    issue(0, 0);
    for (int ci = 0; ci < 8; ci++) {
        if (ci < 7) { issue(ci + 1, (ci + 1) & 1); cp_wait<1>(); }
        else cp_wait<0>();
        __syncthreads();
        const float* xc = xs + (ci & 1) * 4096;
        const float* wc = ws + (ci & 1) * 4096;
        #pragma unroll
        for (int k = 0; k < 32; k++) {
            float4 a0 = *reinterpret_cast<const float4*>(xc + k * 128 + tt * 8);
            float4 a1 = *reinterpret_cast<const float4*>(xc + k * 128 + tt * 8 + 4);
            float4 w0 = *reinterpret_cast<const float4*>(wc + k * 128 + th * 8);
            float4 w1 = *reinterpret_cast<const float4*>(wc + k * 128 + th * 8 + 4);
            float2 wp[4] = { make_float2(w0.x, w0.y), make_float2(w0.z, w0.w),
                             make_float2(w1.x, w1.y), make_float2(w1.z, w1.w) };
            float av[8] = { a0.x, a0.y, a0.z, a0.w, a1.x, a1.y, a1.z, a1.w };
            #pragma unroll
            for (int i = 0; i < 8; i++) {
                float2 ad = dup2(av[i]);
                #pragma unroll
                for (int j = 0; j < 4; j++) acc[i][j] = ffma2(ad, wp[j], acc[i][j]);
            }
        }
        __syncthreads();
    }
    float4 bv0 = *reinterpret_cast<const float4*>(bias + h0 + th * 8);
    float4 bv1 = *reinterpret_cast<const float4*>(bias + h0 + th * 8 + 4);
    #pragma unroll
    for (int i = 0; i < 8; i++) {
        int t = t0 + tt * 8 + i;
        float* zp = g_Z + (size_t)t * (BB * HH) + b * HH + h0 + th * 8;
        float4 o0 = make_float4(acc[i][0].x + bv0.x, acc[i][0].y + bv0.y,
                                acc[i][1].x + bv0.z, acc[i][1].y + bv0.w);
        float4 o1 = make_float4(acc[i][2].x + bv1.x, acc[i][2].y + bv1.y,
                                acc[i][3].x + bv1.z, acc[i][3].y + bv1.w);
        *reinterpret_cast<float4*>(zp)     = o0;
        *reinterpret_cast<float4*>(zp + 4) = o1;
    }
}

// ---------------------------------------------------------------- Kernel B: persistent recurrence (TMA-staged state)
// 128 CTAs: (r in 0..3: 16 batch rows) x (c in 0..31: 32 H cols). Per-r-group barriers.
__global__ void __launch_bounds__(256, 1) rnn_rec_kernel(const float* __restrict__ Wh) {
    extern __shared__ float smem[];
    float* wh_s  = smem + 16;               // [k][32]  32768 floats (128KB)
    float* st_s  = wh_s + 32768;            // [k][16]  16384 floats (64KB)
    float* red_s = st_s + 16384;            // [8][512]  4096 floats (16KB)
    float* fin   = red_s + 4096;            // [16][33]   528 floats
    uint32_t mbar0 = (uint32_t)__cvta_generic_to_shared(smem);

    int tid  = threadIdx.x;
    int wid  = tid >> 5, lane = tid & 31;
    int c = blockIdx.x & 31;                // column tile (32 cols)
    int r = blockIdx.x >> 5;                // batch row group (16 rows)
    int r16 = r * 16;

    if (tid == 0) {
        #pragma unroll
        for (int ch = 0; ch < 4; ch++) mbar_init(mbar0 + ch * 8, 1);
    }
    for (int i = tid; i < 32768; i += 256) {
        int k = i >> 5, n = i & 31;
        wh_s[i] = Wh[k * HH + c * 32 + n];
    }
    __syncthreads();

    int rg = lane >> 3;                     // b-group: rows 4*rg..4*rg+3
    int cg = lane & 7;                      // h-group: cols 4*cg..4*cg+3

    int o  = tid * 2;
    int em = o >> 5, en = o & 31;
    int brow = r16 + em, hcol = c * 32 + en;
    int j2 = tid * 2;
    int hl = j2 >> 4, em2 = j2 & 15;

    float* zbase = g_Z + (size_t)brow * HH + hcol;

    for (int t = 0; t < TT; ++t) {
        // prefetch additive Z term for this step (hidden behind the FMA loop)
        float2 zq = *reinterpret_cast<const float2*>(zbase + (size_t)t * (BB * HH));

        float2 acc[4][2];
        #pragma unroll
        for (int i = 0; i < 4; i++) { acc[i][0] = make_float2(0.f, 0.f); acc[i][1] = make_float2(0.f, 0.f); }

        if (t > 0) {
            int ph = (t - 1) & 1;
            if (wid == 0 && lane < 4) {
                asm volatile("fence.proxy.async;" ::: "memory");
                const float* src = g_ST2[(t + 1) & 1][r];
                int ch = lane;
                uint32_t mb = mbar0 + ch * 8;
                mbar_expect_tx(mb, 16384u);
                uint32_t dst = (uint32_t)__cvta_generic_to_shared(st_s + ch * 4096);
                bulk_g2s(dst, src + ch * 4096, 16384u, mb);
            }
            #pragma unroll
            for (int ch = 0; ch < 4; ch++) {
                mbar_wait(mbar0 + ch * 8, ph);
                int kb = ch * 256 + wid * 32;
                const float* sp = st_s + kb * 16 + rg * 4;
                const float* wp = wh_s + kb * 32 + cg * 4;
                #pragma unroll
                for (int k = 0; k < 32; ++k) {
                    float4 s4 = *reinterpret_cast<const float4*>(sp); sp += 16;
                    float4 wq = *reinterpret_cast<const float4*>(wp); wp += 32;
                    float2 w0 = make_float2(wq.x, wq.y);
                    float2 w1 = make_float2(wq.z, wq.w);
                    acc[0][0] = ffma2(dup2(s4.x), w0, acc[0][0]);
                    acc[0][1] = ffma2(dup2(s4.x), w1, acc[0][1]);
                    acc[1][0] = ffma2(dup2(s4.y), w0, acc[1][0]);
                    acc[1][1] = ffma2(dup2(s4.y), w1, acc[1][1]);
                    acc[2][0] = ffma2(dup2(s4.z), w0, acc[2][0]);
                    acc[2][1] = ffma2(dup2(s4.z), w1, acc[2][1]);
                    acc[3][0] = ffma2(dup2(s4.w), w0, acc[3][0]);
                    acc[3][1] = ffma2(dup2(s4.w), w1, acc[3][1]);
                }
            }
        }

        // cross-warp reduction of K-split partials
        float* rp = red_s + wid * 512 + (rg * 4) * 32 + cg * 4;
        #pragma unroll
        for (int i = 0; i < 4; i++) {
            *reinterpret_cast<float2*>(rp + i * 32)     = acc[i][0];
            *reinterpret_cast<float2*>(rp + i * 32 + 2) = acc[i][1];
        }
        __syncthreads();
        {
            float2 v = make_float2(0.f, 0.f);
            #pragma unroll
            for (int w = 0; w < 8; w++) {
                float2 p = *reinterpret_cast<const float2*>(red_s + w * 512 + o);
                v.x += p.x; v.y += p.y;
            }
            float s0 = tanhf(zq.x + v.x);
            float s1 = tanhf(zq.y + v.y);
            *reinterpret_cast<float2*>(zbase + (size_t)t * (BB * HH)) = make_float2(s0, s1);  // feeds kernel C
            fin[em * 33 + en]     = s0;
            fin[em * 33 + en + 1] = s1;
        }
        __syncthreads();
        {
            float a  = fin[em2 * 33 + hl];
            float b2 = fin[(em2 + 1) * 33 + hl];
            float* stp = g_ST2[t & 1][r] + (size_t)(c * 32 + hl) * 16 + em2;
            *reinterpret_cast<float2*>(stp) = make_float2(a, b2);
        }
        group_barrier(r);
    }
}

// ---------------------------------------------------------------- Kernel C: out[b][t][o] = bout[o] + sum_h S[row][h] * Wout[h][o]
__global__ void __launch_bounds__(256) out_kernel(const float* __restrict__ Wout,
                                                  const float* __restrict__ bout,
                                                  float* __restrict__ out) {
    extern __shared__ float dsm[];
    float* ss = dsm;           // [2][128][32]
    float* ws = dsm + 8192;    // [2][32][128]
    int r0 = blockIdx.x * 128;
    int o0 = blockIdx.y * 128;
    int tid = threadIdx.x;
    int tt = tid >> 4, th = tid & 15;

    float2 acc[8][4];
    #pragma unroll
    for (int i = 0; i < 8; i++)
        #pragma unroll
        for (int j = 0; j < 4; j++) acc[i][j] = make_float2(0.f, 0.f);

    auto issue = [&](int ci, int buf) {
        int f0 = ci * 32;
        float* sd = ss + buf * 4096;
        float* wd = ws + buf * 4096;
        #pragma unroll
        for (int it = 0; it < 4; it++) {
            int idx = it * 256 + tid;
            int ri = idx >> 3, kq = (idx & 7) * 4;
            cp_async16(sd + ri * 32 + kq, g_Z + (size_t)(r0 + ri) * HH + f0 + kq);
            int f = idx >> 5, u = (idx & 31) * 4;
            cp_async16(wd + f * 128 + u, Wout + (f0 + f) * OO + o0 + u);
        }
        cp_commit();
    };

    issue(0, 0);
    for (int ci = 0; ci < 32; ci++) {
        if (ci < 31) { issue(ci + 1, (ci + 1) & 1); cp_wait<1>(); }
        else cp_wait<0>();
        __syncthreads();
        const float* sc = ss + (ci & 1) * 4096;
        const float* wc = ws + (ci & 1) * 4096;
        #pragma unroll
        for (int k = 0; k < 32; k++) {
            float av[8];
            #pragma unroll
            for (int i = 0; i < 8; i++) av[i] = sc[(tt * 8 + i) * 32 + k];
            float4 w0 = *reinterpret_cast<const float4*>(wc + k * 128 + th * 8);
            float4 w1 = *reinterpret_cast<const float4*>(wc + k * 128 + th * 8 + 4);
            float2 wp[4] = { make_float2(w0.x, w0.y), make_float2(w0.z, w0.w),
                             make_float2(w1.x, w1.y), make_float2(w1.z, w1.w) };
            #pragma unroll
            for (int i = 0; i < 8; i++) {
                float2 ad = dup2(av[i]);
                #pragma unroll
                for (int j = 0; j < 4; j++) acc[i][j] = ffma2(ad, wp[j], acc[i][j]);
            }
        }
        __syncthreads();
    }
    float4 bv0 = *reinterpret_cast<const float4*>(bout + o0 + th * 8);
    float4 bv1 = *reinterpret_cast<const float4*>(bout + o0 + th * 8 + 4);
    #pragma unroll
    for (int i = 0; i < 8; i++) {
        int row = r0 + tt * 8 + i;
        int t  = row >> 6;
        int bb = row & 63;
        float* op = out + (size_t)bb * (TT * OO) + t * OO + o0 + th * 8;
        float4 q0 = make_float4(acc[i][0].x + bv0.x, acc[i][0].y + bv0.y,
                                acc[i][1].x + bv0.z, acc[i][1].y + bv0.w);
        float4 q1 = make_float4(acc[i][2].x + bv1.x, acc[i][2].y + bv1.y,
                                acc[i][3].x + bv1.z, acc[i][3].y + bv1.w);
        *reinterpret_cast<float4*>(op)     = q0;
        *reinterpret_cast<float4*>(op + 4) = q1;
    }
}

// ---------------------------------------------------------------- launch
extern "C" void kernel_launch(void* const* d_in, const int* in_sizes, int n_in,
                              void* d_out, int out_size) {
    const float* x    = (const float*)d_in[0];   // (B,F,T)
    const float* Wx   = (const float*)d_in[1];   // (F,H)
    const float* Wh   = (const float*)d_in[2];   // (H,H)
    const float* bv   = (const float*)d_in[3];   // (H,)
    const float* Wout = (const float*)d_in[4];   // (H,O)
    const float* bo   = (const float*)d_in[5];   // (O,)
    float* out = (float*)d_out;                  // (B,T,O)

    (void)in_sizes; (void)n_in; (void)out_size;

    // Phase 1: Z = x@Wx + b (parallel GEMM, double-buffered)
    cudaFuncSetAttribute(zmat_kernel, cudaFuncAttributeMaxDynamicSharedMemorySize, 65536);
    dim3 ga(TT / 128, HH / 128, BB);
    zmat_kernel<<<ga, 256, 65536>>>(x, Wx, bv);

    // Phase 2: persistent sequential recurrence (TMA bulk staging, per-group barriers)
    size_t dyn = (size_t)(16 + 32768 + 16384 + 4096 + 528) * sizeof(float);  // ~215KB
    cudaFuncSetAttribute(rnn_rec_kernel, cudaFuncAttributeMaxDynamicSharedMemorySize, 232448);
    rnn_rec_kernel<<<NB, 256, dyn>>>(Wh);

    // Phase 3: output projection (parallel GEMM, double-buffered)
    cudaFuncSetAttribute(out_kernel, cudaFuncAttributeMaxDynamicSharedMemorySize, 65536);
    dim3 gc((TT * BB) / 128, OO / 128);
    out_kernel<<<gc, 256, 65536>>>(Wout, bo, out);
}